// round 14
// baseline (speedup 1.0000x reference)
#include <cuda_runtime.h>
#include <cuda_fp16.h>
#include <cstdint>
#include <math.h>

// Problem constants
#define Bn   32
#define Sn   2048
#define Dn   1024
#define Mn   (Bn * Sn)

// Score-GEMM tiling (mma.sync HMMA path — tcgen05 PTX is rejected by the
// harness's compute_103 PTX stage, so we use the arch-portable tensor path)
#define BM 128              // CTA rows  (8 warps: 4M x 2N, warp tile 32x64)
#define BN 128              // CTA cols
#define BK 64               // K per chunk
#define NTILES (Dn / BN)    // 8 column tiles
#define NCHUNK (Dn / BK)    // 16 chunks
#define NSTG 3              // 3-stage ring -> single barrier per chunk

#define ROWP 72             // SMEM row stride in halves (144 B = 36 banks ≡ 4
                            // mod 32 -> ldmatrix phases conflict-free)

// ---------------------------------------------------------------------------
// Scratch (static device globals; no allocation allowed)
// ---------------------------------------------------------------------------
__device__ float g_decb[Bn * Dn];                    // dec_h + b_dec + b_enc
__device__ float g_scores_part[NTILES * Mn];         // per-col-tile score partials
__device__ float g_ctx_part[16 * Bn * Dn];           // context partials
__device__ __half g_ench[(size_t)Mn * Dn];           // enc_states fp16 (128 MB)
__device__ __half g_WT[Dn * Dn];                     // W_enc^T fp16 (K-major: [n][k])

// ---------------------------------------------------------------------------
// PTX helpers (sm_80-compatible only: cp.async, ldmatrix, mma.sync)
// ---------------------------------------------------------------------------
__device__ __forceinline__ uint32_t smem_u32(const void* p) {
    uint32_t a;
    asm("{ .reg .u64 t; cvta.to.shared.u64 t, %1; cvt.u32.u64 %0, t; }" : "=r"(a) : "l"(p));
    return a;
}
__device__ __forceinline__ void cp_async16(uint32_t dst, const void* src) {
    asm volatile("cp.async.cg.shared.global [%0], [%1], 16;" :: "r"(dst), "l"(src));
}
__device__ __forceinline__ void cp_commit() {
    asm volatile("cp.async.commit_group;" ::: "memory");
}
template <int N>
__device__ __forceinline__ void cp_wait() {
    asm volatile("cp.async.wait_group %0;" :: "n"(N) : "memory");
}
__device__ __forceinline__ void ldsm4(uint32_t* r, uint32_t addr) {
    asm volatile("ldmatrix.sync.aligned.m8n8.x4.shared.b16 {%0,%1,%2,%3}, [%4];"
                 : "=r"(r[0]), "=r"(r[1]), "=r"(r[2]), "=r"(r[3]) : "r"(addr));
}
__device__ __forceinline__ void mma16816(float* c, const uint32_t* a,
                                         uint32_t b0, uint32_t b1) {
    asm volatile("mma.sync.aligned.m16n8k16.row.col.f32.f16.f16.f32 "
                 "{%0,%1,%2,%3}, {%4,%5,%6,%7}, {%8,%9}, {%0,%1,%2,%3};"
                 : "+f"(c[0]), "+f"(c[1]), "+f"(c[2]), "+f"(c[3])
                 : "r"(a[0]), "r"(a[1]), "r"(a[2]), "r"(a[3]), "r"(b0), "r"(b1));
}

// ---------------------------------------------------------------------------
// Pre-pass A: enc_states fp32 -> fp16 (RN)
// ---------------------------------------------------------------------------
__global__ void convert_enc(const float* __restrict__ enc) {
    size_t i = (size_t)blockIdx.x * blockDim.x + threadIdx.x;  // one float4 each
    float4 v = reinterpret_cast<const float4*>(enc)[i];
    __half2 p0 = __floats2half2_rn(v.x, v.y);
    __half2 p1 = __floats2half2_rn(v.z, v.w);
    uint2 u;
    u.x = *reinterpret_cast<uint32_t*>(&p0);
    u.y = *reinterpret_cast<uint32_t*>(&p1);
    reinterpret_cast<uint2*>(g_ench)[i] = u;
}

// ---------------------------------------------------------------------------
// Pre-pass B: W_enc [K,N] fp32 -> transposed K-major fp16
// ---------------------------------------------------------------------------
__global__ void convert_W(const float* __restrict__ W) {
    int n = blockIdx.x;
    int k = threadIdx.x;
    g_WT[(size_t)n * Dn + k] = __float2half_rn(W[(size_t)k * Dn + n]);
}

// ---------------------------------------------------------------------------
// decb[b,c] = b_dec[c] + b_enc[c] + dec_states[b,:] @ W_dec[:,c]
// ---------------------------------------------------------------------------
__global__ void dech_kernel(const float* __restrict__ dec,
                            const float* __restrict__ Wdec,
                            const float* __restrict__ bdec,
                            const float* __restrict__ benc) {
    const int b   = blockIdx.x;
    const int c   = blockIdx.y * 256 + threadIdx.x;
    __shared__ float dsh[Dn];
    for (int k = threadIdx.x; k < Dn; k += 256) dsh[k] = dec[b * Dn + k];
    __syncthreads();
    float acc = bdec[c] + benc[c];
    #pragma unroll 8
    for (int k = 0; k < Dn; k++)
        acc = fmaf(dsh[k], Wdec[(size_t)k * Dn + c], acc);
    g_decb[b * Dn + c] = acc;
}

// ---------------------------------------------------------------------------
// HMMA fused score GEMM (fp16, BK=64, 3-stage ring, frag double-buffering).
//  D[128,128] = A_fp16[128,K] @ B_fp16[128,K]^T  (fp32 accum)
//  epilogue: rowsum of tanh(D + decb) * w_attn -> g_scores_part[tile_n][row]
//  8 warps, 4(M) x 2(N); warp tile 32x64.
//  Frag pipeline: LDSMs for k-step kk+1 are issued BEFORE the 16 MMAs of
//  k-step kk (separate register buffer), hiding the LDSM result latency under
//  the 128-cycle MMA burst (R13 showed ~200 exposed idle cyc/SMSP/k-step-pair
//  with both warps stalling on LDSM in lockstep).
// ---------------------------------------------------------------------------
struct Stage {
    __half A[BM][ROWP];    // 18432 B
    __half B[BN][ROWP];    // 18432 B
};
#define B_OFF  (BM * ROWP * 2)             // byte offset of B within a stage
#define SMEM_BYTES (NSTG * (int)sizeof(Stage) + (BN + BN + 2 * BM) * 4)

__global__ __launch_bounds__(256)
void score_gemm_hmma(const float* __restrict__ wattn) {
    extern __shared__ char dsm[];
    float* s_db   = reinterpret_cast<float*>(dsm + NSTG * sizeof(Stage));
    float* s_w    = s_db + BN;
    float* rowsum = s_w + BN;                 // [2][BM]

    const int tid  = threadIdx.x;
    const int wid  = tid >> 5;
    const int lane = tid & 31;
    const int wm   = wid >> 1;     // 0..3 : 32-row group
    const int wn   = wid & 1;      // 0..1 : 64-col group
    const int n0   = blockIdx.x * BN;   // x = col tile -> CTAs share A in L2
    const int m0   = blockIdx.y * BM;
    const int b    = m0 >> 11;

    if (tid < BN) {
        s_db[tid] = g_decb[b * Dn + n0 + tid];
        s_w[tid]  = wattn[n0 + tid];
    }

    float acc[2][8][4];            // [mi][nf][frag] : 64 regs
    #pragma unroll
    for (int i = 0; i < 2; i++)
        #pragma unroll
        for (int j = 0; j < 8; j++)
            #pragma unroll
            for (int q = 0; q < 4; q++) acc[i][j][q] = 0.f;

    // ---- hoisted loader addressing ----
    const int s8 = (tid & 7) * 8;             // half offset within 64-half row
    const int r0 = tid >> 3;                  // 0..31
    const __half* aSrc = g_ench + ((size_t)m0 + r0) * Dn + s8;
    const __half* bSrc = g_WT + (size_t)(n0 + r0) * Dn + s8;
    uint32_t stgAddr[NSTG];
    #pragma unroll
    for (int s = 0; s < NSTG; s++) stgAddr[s] = smem_u32(dsm + s * sizeof(Stage));
    const uint32_t aDst = r0 * (ROWP * 2) + s8 * 2;           // within stage
    const uint32_t bDst = B_OFF + r0 * (ROWP * 2) + s8 * 2;

    auto load_chunk = [&](int c) {
        const uint32_t base = stgAddr[c % NSTG];
        const int k0 = c * BK;
        #pragma unroll
        for (int i = 0; i < 4; i++)           // A: 4 x 32 rows
            cp_async16(base + aDst + i * (32 * ROWP * 2),
                       aSrc + k0 + (size_t)i * 32 * Dn);
        #pragma unroll
        for (int i = 0; i < 4; i++)           // B: 4 x 32 rows
            cp_async16(base + bDst + i * (32 * ROWP * 2),
                       bSrc + k0 + (size_t)i * 32 * Dn);
        cp_commit();
    };

    // ---- hoisted ldmatrix addressing ----
    const uint32_t aLd = (wm * 32 + (lane & 15)) * (ROWP * 2) + (lane >> 4) * 16;
    const int quad = lane >> 3;
    const uint32_t bLd = B_OFF
        + (wn * 64 + ((quad & 2) ? 8 : 0) + (lane & 7)) * (ROWP * 2)
        + ((quad & 1) ? 16 : 0);

    // Double-buffered fragment registers
    uint32_t afr[2][2][4];         // [buf][mi][frag]
    uint32_t bfr[2][4][4];         // [buf][p][frag]

    load_chunk(0);
    load_chunk(1);

    for (int c = 0; c < NCHUNK; c++) {
        cp_wait<1>();                 // chunk c landed (c+1 may stay in flight)
        __syncthreads();              // all warps see it; stage (c+2)%3 is free
        if (c + 2 < NCHUNK) load_chunk(c + 2);   // overlaps compute below
        const uint32_t base = stgAddr[c % NSTG];

        // Preload frags for kk=0 into buffer 0
        #pragma unroll
        for (int mi = 0; mi < 2; mi++)
            ldsm4(afr[0][mi], base + aLd + mi * (16 * ROWP * 2));
        #pragma unroll
        for (int p = 0; p < 4; p++)
            ldsm4(bfr[0][p], base + bLd + p * (16 * ROWP * 2));

        #pragma unroll
        for (int kk = 0; kk < 4; kk++) {              // four k16 steps per chunk
            const int cur = kk & 1;
            const int nxt = cur ^ 1;
            // Issue next k-step's LDSMs first (independent regs) so their
            // latency hides under the 16-MMA burst below.
            if (kk < 3) {
                const uint32_t kboff = (kk + 1) * 32; // bytes
                #pragma unroll
                for (int mi = 0; mi < 2; mi++)
                    ldsm4(afr[nxt][mi], base + aLd + mi * (16 * ROWP * 2) + kboff);
                #pragma unroll
                for (int p = 0; p < 4; p++)
                    ldsm4(bfr[nxt][p], base + bLd + p * (16 * ROWP * 2) + kboff);
            }
            // 16 independent MMAs (16 distinct accumulators)
            #pragma unroll
            for (int mi = 0; mi < 2; mi++)
                #pragma unroll
                for (int nf = 0; nf < 8; nf++)
                    mma16816(acc[mi][nf], afr[cur][mi],
                             bfr[cur][nf >> 1][(nf & 1) * 2],
                             bfr[cur][nf >> 1][(nf & 1) * 2 + 1]);
        }
    }

    // Epilogue: rowsum of tanh(acc + decb) * w_attn
    // c-frag: c0,c1 -> row lane/4, cols 2*(lane%4)+{0,1}; c2,c3 -> row +8
    __syncthreads();                  // loads done; reuse of rowsum region safe
    #pragma unroll
    for (int mi = 0; mi < 2; mi++) {
        float sl = 0.f, sh = 0.f;
        #pragma unroll
        for (int nf = 0; nf < 8; nf++) {
            int cb = wn * 64 + nf * 8 + (lane & 3) * 2;
            sl += tanhf(acc[mi][nf][0] + s_db[cb])     * s_w[cb]
                + tanhf(acc[mi][nf][1] + s_db[cb + 1]) * s_w[cb + 1];
            sh += tanhf(acc[mi][nf][2] + s_db[cb])     * s_w[cb]
                + tanhf(acc[mi][nf][3] + s_db[cb + 1]) * s_w[cb + 1];
        }
        sl += __shfl_xor_sync(0xffffffffu, sl, 1);
        sl += __shfl_xor_sync(0xffffffffu, sl, 2);
        sh += __shfl_xor_sync(0xffffffffu, sh, 1);
        sh += __shfl_xor_sync(0xffffffffu, sh, 2);
        if ((lane & 3) == 0) {
            int r = wm * 32 + mi * 16 + (lane >> 2);
            rowsum[wn * BM + r]     = sl;
            rowsum[wn * BM + r + 8] = sh;
        }
    }
    __syncthreads();
    if (tid < BM)
        g_scores_part[blockIdx.x * Mn + m0 + tid] = rowsum[tid] + rowsum[BM + tid];
}

// ---------------------------------------------------------------------------
// Masked softmax per batch row; writes attn into d_out[32768 + b*2048 + s]
// ---------------------------------------------------------------------------
__global__ void softmax_kernel(const int* __restrict__ enc_len,
                               float* __restrict__ attn_out) {
    const int b = blockIdx.x;
    const int tid = threadIdx.x;
    __shared__ float red[256];
    __shared__ float sc[Sn];

    const int len = enc_len[b];

    float lmax = -INFINITY;
    for (int s = tid; s < Sn; s += 256) {
        float v = 0.f;
        #pragma unroll
        for (int ct = 0; ct < NTILES; ct++)
            v += g_scores_part[ct * Mn + b * Sn + s];
        sc[s] = v;
        if (s < len) lmax = fmaxf(lmax, v);
    }
    red[tid] = lmax;
    __syncthreads();
    for (int off = 128; off > 0; off >>= 1) {
        if (tid < off) red[tid] = fmaxf(red[tid], red[tid + off]);
        __syncthreads();
    }
    const float m = red[0];
    __syncthreads();

    float lsum = 0.f;
    for (int s = tid; s < Sn; s += 256) {
        float e = (s < len) ? expf(sc[s] - m) : 0.f;
        sc[s] = e;
        lsum += e;
    }
    red[tid] = lsum;
    __syncthreads();
    for (int off = 128; off > 0; off >>= 1) {
        if (tid < off) red[tid] += red[tid + off];
        __syncthreads();
    }
    const float inv = 1.f / red[0];
    __syncthreads();

    for (int s = tid; s < Sn; s += 256)
        attn_out[b * Sn + s] = sc[s] * inv;
}

// ---------------------------------------------------------------------------
// Context partials (fp32 enc_states for accuracy; near DRAM roofline already)
// ---------------------------------------------------------------------------
__global__ void context_kernel(const float* __restrict__ enc,
                               const float* __restrict__ attn) {
    const int ch = blockIdx.x;
    const int b = blockIdx.y;
    const int tid = threadIdx.x;
    const int d = tid * 4;
    __shared__ float wsh[128];
    if (tid < 128) wsh[tid] = attn[b * Sn + ch * 128 + tid];
    __syncthreads();

    float4 acc = make_float4(0.f, 0.f, 0.f, 0.f);
    const int s0 = ch * 128;
    for (int i = 0; i < 128; i++) {
        float w = wsh[i];
        float4 e = *reinterpret_cast<const float4*>(
            &enc[((size_t)b * Sn + s0 + i) * Dn + d]);
        acc.x = fmaf(w, e.x, acc.x);
        acc.y = fmaf(w, e.y, acc.y);
        acc.z = fmaf(w, e.z, acc.z);
        acc.w = fmaf(w, e.w, acc.w);
    }
    *reinterpret_cast<float4*>(&g_ctx_part[((size_t)ch * Bn + b) * Dn + d]) = acc;
}

// ---------------------------------------------------------------------------
// Output GEMM
// ---------------------------------------------------------------------------
__global__ void out_kernel(const float* __restrict__ Wout,
                           const float* __restrict__ bout,
                           float* __restrict__ out) {
    const int b = blockIdx.x;
    const int c = blockIdx.y * 256 + threadIdx.x;
    __shared__ float ctx[Dn];
    for (int k = threadIdx.x; k < Dn; k += 256) {
        float v = 0.f;
        #pragma unroll
        for (int ch = 0; ch < 16; ch++)
            v += g_ctx_part[((size_t)ch * Bn + b) * Dn + k];
        ctx[k] = v;
    }
    __syncthreads();
    float acc = bout[c];
    #pragma unroll 8
    for (int k = 0; k < Dn; k++)
        acc = fmaf(ctx[k], Wout[(size_t)k * Dn + c], acc);
    out[b * Dn + c] = acc;
}

// ---------------------------------------------------------------------------
// Launch
// ---------------------------------------------------------------------------
extern "C" void kernel_launch(void* const* d_in, const int* in_sizes, int n_in,
                              void* d_out, int out_size) {
    const float* enc   = (const float*)d_in[0];
    const float* dec   = (const float*)d_in[1];
    const float* Wenc  = (const float*)d_in[2];
    const float* benc  = (const float*)d_in[3];
    const float* Wdec  = (const float*)d_in[4];
    const float* bdec  = (const float*)d_in[5];
    const float* wattn = (const float*)d_in[6];
    const float* Wout  = (const float*)d_in[7];
    const float* bout  = (const float*)d_in[8];
    const int*   elen  = (const int*)d_in[9];

    float* out      = (float*)d_out;       // context [32*1024]
    float* attn_out = out + Bn * Dn;       // attn    [32*2048]

    cudaFuncSetAttribute(score_gemm_hmma,
                         cudaFuncAttributeMaxDynamicSharedMemorySize, SMEM_BYTES);

    convert_enc<<<(Mn * (Dn / 4)) / 256, 256>>>(enc);
    convert_W<<<Dn, Dn>>>(Wenc);
    dech_kernel<<<dim3(Bn, 4), 256>>>(dec, Wdec, bdec, benc);
    score_gemm_hmma<<<dim3(NTILES, Mn / BM), 256, SMEM_BYTES>>>(wattn);
    softmax_kernel<<<Bn, 256>>>(elen, attn_out);
    context_kernel<<<dim3(16, Bn), 256>>>(enc, attn_out);
    out_kernel<<<dim3(Bn, 4), 256>>>(Wout, bout, out);
}

// round 15
// speedup vs baseline: 1.4467x; 1.4467x over previous
#include <cuda_runtime.h>
#include <cuda_fp16.h>
#include <cstdint>
#include <math.h>

// Problem constants
#define Bn   32
#define Sn   2048
#define Dn   1024
#define Mn   (Bn * Sn)

// Score-GEMM tiling (mma.sync HMMA path — tcgen05 PTX is rejected by the
// harness's compute_103 PTX stage, so we use the arch-portable tensor path)
#define BM 128              // CTA rows  (8 warps: 4M x 2N, warp tile 32x64)
#define BN 128              // CTA cols
#define BK 64               // K per chunk
#define NTILES (Dn / BN)    // 8 column tiles
#define NCHUNK (Dn / BK)    // 16 chunks
#define NSTG 3              // 3-stage ring -> single barrier per chunk

#define ROWP 72             // SMEM row stride in halves (144 B = 36 banks ≡ 4
                            // mod 32 -> ldmatrix phases conflict-free)

// ---------------------------------------------------------------------------
// Scratch (static device globals; no allocation allowed)
// ---------------------------------------------------------------------------
__device__ float g_decb[Bn * Dn];                    // dec_h + b_dec + b_enc
__device__ float g_scores_part[NTILES * Mn];         // per-col-tile score partials
__device__ float g_ctx_part[16 * Bn * Dn];           // context partials
__device__ __half g_ench[(size_t)Mn * Dn];           // enc_states fp16 (128 MB)
__device__ __half g_WT[Dn * Dn];                     // W_enc^T fp16 (K-major: [n][k])

// ---------------------------------------------------------------------------
// PTX helpers (sm_80-compatible only: cp.async, ldmatrix, mma.sync)
// ---------------------------------------------------------------------------
__device__ __forceinline__ uint32_t smem_u32(const void* p) {
    uint32_t a;
    asm("{ .reg .u64 t; cvta.to.shared.u64 t, %1; cvt.u32.u64 %0, t; }" : "=r"(a) : "l"(p));
    return a;
}
__device__ __forceinline__ void cp_async16(uint32_t dst, const void* src) {
    asm volatile("cp.async.cg.shared.global [%0], [%1], 16;" :: "r"(dst), "l"(src));
}
__device__ __forceinline__ void cp_commit() {
    asm volatile("cp.async.commit_group;" ::: "memory");
}
template <int N>
__device__ __forceinline__ void cp_wait() {
    asm volatile("cp.async.wait_group %0;" :: "n"(N) : "memory");
}
__device__ __forceinline__ void ldsm4(uint32_t* r, uint32_t addr) {
    asm volatile("ldmatrix.sync.aligned.m8n8.x4.shared.b16 {%0,%1,%2,%3}, [%4];"
                 : "=r"(r[0]), "=r"(r[1]), "=r"(r[2]), "=r"(r[3]) : "r"(addr));
}
__device__ __forceinline__ void mma16816(float* c, const uint32_t* a,
                                         uint32_t b0, uint32_t b1) {
    asm volatile("mma.sync.aligned.m16n8k16.row.col.f32.f16.f16.f32 "
                 "{%0,%1,%2,%3}, {%4,%5,%6,%7}, {%8,%9}, {%0,%1,%2,%3};"
                 : "+f"(c[0]), "+f"(c[1]), "+f"(c[2]), "+f"(c[3])
                 : "r"(a[0]), "r"(a[1]), "r"(a[2]), "r"(a[3]), "r"(b0), "r"(b1));
}

// ---------------------------------------------------------------------------
// Pre-pass A: enc_states fp32 -> fp16 (RN)
// ---------------------------------------------------------------------------
__global__ void convert_enc(const float* __restrict__ enc) {
    size_t i = (size_t)blockIdx.x * blockDim.x + threadIdx.x;  // one float4 each
    float4 v = reinterpret_cast<const float4*>(enc)[i];
    __half2 p0 = __floats2half2_rn(v.x, v.y);
    __half2 p1 = __floats2half2_rn(v.z, v.w);
    uint2 u;
    u.x = *reinterpret_cast<uint32_t*>(&p0);
    u.y = *reinterpret_cast<uint32_t*>(&p1);
    reinterpret_cast<uint2*>(g_ench)[i] = u;
}

// ---------------------------------------------------------------------------
// Pre-pass B: W_enc [K,N] fp32 -> transposed K-major fp16
// ---------------------------------------------------------------------------
__global__ void convert_W(const float* __restrict__ W) {
    int n = blockIdx.x;
    int k = threadIdx.x;
    g_WT[(size_t)n * Dn + k] = __float2half_rn(W[(size_t)k * Dn + n]);
}

// ---------------------------------------------------------------------------
// decb[b,c] = b_dec[c] + b_enc[c] + dec_states[b,:] @ W_dec[:,c]
// ---------------------------------------------------------------------------
__global__ void dech_kernel(const float* __restrict__ dec,
                            const float* __restrict__ Wdec,
                            const float* __restrict__ bdec,
                            const float* __restrict__ benc) {
    const int b   = blockIdx.x;
    const int c   = blockIdx.y * 256 + threadIdx.x;
    __shared__ float dsh[Dn];
    for (int k = threadIdx.x; k < Dn; k += 256) dsh[k] = dec[b * Dn + k];
    __syncthreads();
    float acc = bdec[c] + benc[c];
    #pragma unroll 8
    for (int k = 0; k < Dn; k++)
        acc = fmaf(dsh[k], Wdec[(size_t)k * Dn + c], acc);
    g_decb[b * Dn + c] = acc;
}

// ---------------------------------------------------------------------------
// HMMA fused score GEMM (fp16, BK=64, 3-stage ring; R13 structure).
//  D[128,128] = A_fp16[128,K] @ B_fp16[128,K]^T  (fp32 accum)
//  epilogue: rowsum of tanh(D + decb) * w_attn -> g_scores_part[tile_n][row]
//  8 warps, 4(M) x 2(N); warp tile 32x64.
//  R14 lesson: NO extra frag buffers (spilled at 64 acc regs). Instead the
//  B LDSMs are interleaved between MMA groups — zero-register ordering change
//  that gives each LDSM a ~4-MMA shadow.
// ---------------------------------------------------------------------------
struct Stage {
    __half A[BM][ROWP];    // 18432 B
    __half B[BN][ROWP];    // 18432 B
};
#define B_OFF  (BM * ROWP * 2)             // byte offset of B within a stage
#define SMEM_BYTES (NSTG * (int)sizeof(Stage) + (BN + BN + 2 * BM) * 4)

__global__ __launch_bounds__(256)
void score_gemm_hmma(const float* __restrict__ wattn) {
    extern __shared__ char dsm[];
    float* s_db   = reinterpret_cast<float*>(dsm + NSTG * sizeof(Stage));
    float* s_w    = s_db + BN;
    float* rowsum = s_w + BN;                 // [2][BM]

    const int tid  = threadIdx.x;
    const int wid  = tid >> 5;
    const int lane = tid & 31;
    const int wm   = wid >> 1;     // 0..3 : 32-row group
    const int wn   = wid & 1;      // 0..1 : 64-col group
    const int n0   = blockIdx.x * BN;   // x = col tile -> CTAs share A in L2
    const int m0   = blockIdx.y * BM;
    const int b    = m0 >> 11;

    if (tid < BN) {
        s_db[tid] = g_decb[b * Dn + n0 + tid];
        s_w[tid]  = wattn[n0 + tid];
    }

    float acc[2][8][4];            // [mi][nf][frag] : 64 regs
    #pragma unroll
    for (int i = 0; i < 2; i++)
        #pragma unroll
        for (int j = 0; j < 8; j++)
            #pragma unroll
            for (int q = 0; q < 4; q++) acc[i][j][q] = 0.f;

    // ---- hoisted loader addressing ----
    const int s8 = (tid & 7) * 8;             // half offset within 64-half row
    const int r0 = tid >> 3;                  // 0..31
    const __half* aSrc = g_ench + ((size_t)m0 + r0) * Dn + s8;
    const __half* bSrc = g_WT + (size_t)(n0 + r0) * Dn + s8;
    uint32_t stgAddr[NSTG];
    #pragma unroll
    for (int s = 0; s < NSTG; s++) stgAddr[s] = smem_u32(dsm + s * sizeof(Stage));
    const uint32_t aDst = r0 * (ROWP * 2) + s8 * 2;           // within stage
    const uint32_t bDst = B_OFF + r0 * (ROWP * 2) + s8 * 2;

    auto load_chunk = [&](int c) {
        const uint32_t base = stgAddr[c % NSTG];
        const int k0 = c * BK;
        #pragma unroll
        for (int i = 0; i < 4; i++)           // A: 4 x 32 rows
            cp_async16(base + aDst + i * (32 * ROWP * 2),
                       aSrc + k0 + (size_t)i * 32 * Dn);
        #pragma unroll
        for (int i = 0; i < 4; i++)           // B: 4 x 32 rows
            cp_async16(base + bDst + i * (32 * ROWP * 2),
                       bSrc + k0 + (size_t)i * 32 * Dn);
        cp_commit();
    };

    // ---- hoisted ldmatrix addressing ----
    const uint32_t aLd = (wm * 32 + (lane & 15)) * (ROWP * 2) + (lane >> 4) * 16;
    const int quad = lane >> 3;
    const uint32_t bLd = B_OFF
        + (wn * 64 + ((quad & 2) ? 8 : 0) + (lane & 7)) * (ROWP * 2)
        + ((quad & 1) ? 16 : 0);

    load_chunk(0);
    load_chunk(1);

    for (int c = 0; c < NCHUNK; c++) {
        cp_wait<1>();                 // chunk c landed (c+1 may stay in flight)
        __syncthreads();              // all warps see it; stage (c+2)%3 is free
        if (c + 2 < NCHUNK) load_chunk(c + 2);   // overlaps compute below
        const uint32_t base = stgAddr[c % NSTG];

        #pragma unroll
        for (int kk = 0; kk < 4; kk++) {              // four k16 steps per chunk
            const uint32_t kboff = kk * 32;           // kb*2 bytes
            uint32_t a[2][4];
            ldsm4(a[0], base + aLd + kboff);
            ldsm4(a[1], base + aLd + (16 * ROWP * 2) + kboff);
            uint32_t bf[4][4];
            ldsm4(bf[0], base + bLd + kboff);
            ldsm4(bf[1], base + bLd + (16 * ROWP * 2) + kboff);
            // MMAs on bf0 (nf 0,1) while bf2 loads
            #pragma unroll
            for (int mi = 0; mi < 2; mi++) {
                mma16816(acc[mi][0], a[mi], bf[0][0], bf[0][1]);
                mma16816(acc[mi][1], a[mi], bf[0][2], bf[0][3]);
            }
            ldsm4(bf[2], base + bLd + 2 * (16 * ROWP * 2) + kboff);
            #pragma unroll
            for (int mi = 0; mi < 2; mi++) {
                mma16816(acc[mi][2], a[mi], bf[1][0], bf[1][1]);
                mma16816(acc[mi][3], a[mi], bf[1][2], bf[1][3]);
            }
            ldsm4(bf[3], base + bLd + 3 * (16 * ROWP * 2) + kboff);
            #pragma unroll
            for (int mi = 0; mi < 2; mi++) {
                mma16816(acc[mi][4], a[mi], bf[2][0], bf[2][1]);
                mma16816(acc[mi][5], a[mi], bf[2][2], bf[2][3]);
            }
            #pragma unroll
            for (int mi = 0; mi < 2; mi++) {
                mma16816(acc[mi][6], a[mi], bf[3][0], bf[3][1]);
                mma16816(acc[mi][7], a[mi], bf[3][2], bf[3][3]);
            }
        }
    }

    // Epilogue: rowsum of tanh(acc + decb) * w_attn
    // c-frag: c0,c1 -> row lane/4, cols 2*(lane%4)+{0,1}; c2,c3 -> row +8
    __syncthreads();                  // loads done; reuse of rowsum region safe
    #pragma unroll
    for (int mi = 0; mi < 2; mi++) {
        float sl = 0.f, sh = 0.f;
        #pragma unroll
        for (int nf = 0; nf < 8; nf++) {
            int cb = wn * 64 + nf * 8 + (lane & 3) * 2;
            sl += tanhf(acc[mi][nf][0] + s_db[cb])     * s_w[cb]
                + tanhf(acc[mi][nf][1] + s_db[cb + 1]) * s_w[cb + 1];
            sh += tanhf(acc[mi][nf][2] + s_db[cb])     * s_w[cb]
                + tanhf(acc[mi][nf][3] + s_db[cb + 1]) * s_w[cb + 1];
        }
        sl += __shfl_xor_sync(0xffffffffu, sl, 1);
        sl += __shfl_xor_sync(0xffffffffu, sl, 2);
        sh += __shfl_xor_sync(0xffffffffu, sh, 1);
        sh += __shfl_xor_sync(0xffffffffu, sh, 2);
        if ((lane & 3) == 0) {
            int r = wm * 32 + mi * 16 + (lane >> 2);
            rowsum[wn * BM + r]     = sl;
            rowsum[wn * BM + r + 8] = sh;
        }
    }
    __syncthreads();
    if (tid < BM)
        g_scores_part[blockIdx.x * Mn + m0 + tid] = rowsum[tid] + rowsum[BM + tid];
}

// ---------------------------------------------------------------------------
// Masked softmax per batch row; writes attn into d_out[32768 + b*2048 + s]
// ---------------------------------------------------------------------------
__global__ void softmax_kernel(const int* __restrict__ enc_len,
                               float* __restrict__ attn_out) {
    const int b = blockIdx.x;
    const int tid = threadIdx.x;
    __shared__ float red[256];
    __shared__ float sc[Sn];

    const int len = enc_len[b];

    float lmax = -INFINITY;
    for (int s = tid; s < Sn; s += 256) {
        float v = 0.f;
        #pragma unroll
        for (int ct = 0; ct < NTILES; ct++)
            v += g_scores_part[ct * Mn + b * Sn + s];
        sc[s] = v;
        if (s < len) lmax = fmaxf(lmax, v);
    }
    red[tid] = lmax;
    __syncthreads();
    for (int off = 128; off > 0; off >>= 1) {
        if (tid < off) red[tid] = fmaxf(red[tid], red[tid + off]);
        __syncthreads();
    }
    const float m = red[0];
    __syncthreads();

    float lsum = 0.f;
    for (int s = tid; s < Sn; s += 256) {
        float e = (s < len) ? expf(sc[s] - m) : 0.f;
        sc[s] = e;
        lsum += e;
    }
    red[tid] = lsum;
    __syncthreads();
    for (int off = 128; off > 0; off >>= 1) {
        if (tid < off) red[tid] += red[tid + off];
        __syncthreads();
    }
    const float inv = 1.f / red[0];
    __syncthreads();

    for (int s = tid; s < Sn; s += 256)
        attn_out[b * Sn + s] = sc[s] * inv;
}

// ---------------------------------------------------------------------------
// Context partials — now reads fp16 g_ench (halves the 75%-DRAM-bound
// traffic of this kernel; adds ~3e-4 rms rel err to context, inside budget).
// 128 threads x 8 dims each.
// ---------------------------------------------------------------------------
__global__ void context_kernel(const float* __restrict__ attn) {
    const int ch = blockIdx.x;
    const int b = blockIdx.y;
    const int tid = threadIdx.x;    // 0..127
    const int d = tid * 8;
    __shared__ float wsh[128];
    wsh[tid] = attn[b * Sn + ch * 128 + tid];
    __syncthreads();

    float acc[8];
    #pragma unroll
    for (int j = 0; j < 8; j++) acc[j] = 0.f;
    const int s0 = ch * 128;
    const __half* __restrict__ ebase = g_ench + ((size_t)b * Sn + s0) * Dn + d;
    for (int i = 0; i < 128; i++) {
        float w = wsh[i];
        uint4 raw = *reinterpret_cast<const uint4*>(ebase + (size_t)i * Dn);
        const __half2* h2 = reinterpret_cast<const __half2*>(&raw);
        #pragma unroll
        for (int j = 0; j < 4; j++) {
            float2 f = __half22float2(h2[j]);
            acc[2 * j]     = fmaf(w, f.x, acc[2 * j]);
            acc[2 * j + 1] = fmaf(w, f.y, acc[2 * j + 1]);
        }
    }
    float* dst = &g_ctx_part[((size_t)ch * Bn + b) * Dn + d];
    #pragma unroll
    for (int j = 0; j < 8; j += 4)
        *reinterpret_cast<float4*>(dst + j) =
            make_float4(acc[j], acc[j + 1], acc[j + 2], acc[j + 3]);
}

// ---------------------------------------------------------------------------
// Output GEMM
// ---------------------------------------------------------------------------
__global__ void out_kernel(const float* __restrict__ Wout,
                           const float* __restrict__ bout,
                           float* __restrict__ out) {
    const int b = blockIdx.x;
    const int c = blockIdx.y * 256 + threadIdx.x;
    __shared__ float ctx[Dn];
    for (int k = threadIdx.x; k < Dn; k += 256) {
        float v = 0.f;
        #pragma unroll
        for (int ch = 0; ch < 16; ch++)
            v += g_ctx_part[((size_t)ch * Bn + b) * Dn + k];
        ctx[k] = v;
    }
    __syncthreads();
    float acc = bout[c];
    #pragma unroll 8
    for (int k = 0; k < Dn; k++)
        acc = fmaf(ctx[k], Wout[(size_t)k * Dn + c], acc);
    out[b * Dn + c] = acc;
}

// ---------------------------------------------------------------------------
// Launch
// ---------------------------------------------------------------------------
extern "C" void kernel_launch(void* const* d_in, const int* in_sizes, int n_in,
                              void* d_out, int out_size) {
    const float* enc   = (const float*)d_in[0];
    const float* dec   = (const float*)d_in[1];
    const float* Wenc  = (const float*)d_in[2];
    const float* benc  = (const float*)d_in[3];
    const float* Wdec  = (const float*)d_in[4];
    const float* bdec  = (const float*)d_in[5];
    const float* wattn = (const float*)d_in[6];
    const float* Wout  = (const float*)d_in[7];
    const float* bout  = (const float*)d_in[8];
    const int*   elen  = (const int*)d_in[9];

    float* out      = (float*)d_out;       // context [32*1024]
    float* attn_out = out + Bn * Dn;       // attn    [32*2048]

    cudaFuncSetAttribute(score_gemm_hmma,
                         cudaFuncAttributeMaxDynamicSharedMemorySize, SMEM_BYTES);

    convert_enc<<<(Mn * (Dn / 4)) / 256, 256>>>(enc);
    convert_W<<<Dn, Dn>>>(Wenc);
    dech_kernel<<<dim3(Bn, 4), 256>>>(dec, Wdec, bdec, benc);
    score_gemm_hmma<<<dim3(NTILES, Mn / BM), 256, SMEM_BYTES>>>(wattn);
    softmax_kernel<<<Bn, 256>>>(elen, attn_out);
    context_kernel<<<dim3(16, Bn), 128>>>(attn_out);
    out_kernel<<<dim3(Bn, 4), 256>>>(Wout, bout, out);
}

// round 16
// speedup vs baseline: 1.6967x; 1.1728x over previous
#include <cuda_runtime.h>
#include <cuda_fp16.h>
#include <cstdint>
#include <math.h>

// Problem constants
#define Bn   32
#define Sn   2048
#define Dn   1024
#define Mn   (Bn * Sn)

// Score-GEMM tiling (mma.sync HMMA path — tcgen05 PTX is rejected by the
// harness's compute_103 PTX stage, so we use the arch-portable tensor path)
#define BM 128              // CTA rows  (8 warps: 4M x 2N, warp tile 32x64)
#define BN 128              // CTA cols
#define BK 64               // K per chunk
#define NTILES (Dn / BN)    // 8 column tiles
#define NCHUNK (Dn / BK)    // 16 chunks
#define NSTG 3              // 3-stage ring -> single barrier per chunk

#define ROWP 72             // SMEM row stride in halves (144 B = 36 banks ≡ 4
                            // mod 32 -> ldmatrix phases conflict-free)

#define CCH 32              // context: 32 chunks of 64 seq positions

// ---------------------------------------------------------------------------
// Scratch (static device globals; no allocation allowed)
// ---------------------------------------------------------------------------
__device__ float g_decb[Bn * Dn];                    // dec_h + b_dec + b_enc
__device__ float g_scores_part[NTILES * Mn];         // per-col-tile score partials
__device__ float g_ctx_part[CCH * Bn * Dn];          // context partials
__device__ __half g_ench[(size_t)Mn * Dn];           // enc_states fp16 (128 MB)
__device__ __half g_WT[Dn * Dn];                     // W_enc^T fp16 (K-major: [n][k])

// ---------------------------------------------------------------------------
// PTX helpers (sm_80-compatible only: cp.async, ldmatrix, mma.sync)
// ---------------------------------------------------------------------------
__device__ __forceinline__ uint32_t smem_u32(const void* p) {
    uint32_t a;
    asm("{ .reg .u64 t; cvta.to.shared.u64 t, %1; cvt.u32.u64 %0, t; }" : "=r"(a) : "l"(p));
    return a;
}
__device__ __forceinline__ void cp_async16(uint32_t dst, const void* src) {
    asm volatile("cp.async.cg.shared.global [%0], [%1], 16;" :: "r"(dst), "l"(src));
}
__device__ __forceinline__ void cp_commit() {
    asm volatile("cp.async.commit_group;" ::: "memory");
}
template <int N>
__device__ __forceinline__ void cp_wait() {
    asm volatile("cp.async.wait_group %0;" :: "n"(N) : "memory");
}
__device__ __forceinline__ void ldsm4(uint32_t* r, uint32_t addr) {
    asm volatile("ldmatrix.sync.aligned.m8n8.x4.shared.b16 {%0,%1,%2,%3}, [%4];"
                 : "=r"(r[0]), "=r"(r[1]), "=r"(r[2]), "=r"(r[3]) : "r"(addr));
}
__device__ __forceinline__ void mma16816(float* c, const uint32_t* a,
                                         uint32_t b0, uint32_t b1) {
    asm volatile("mma.sync.aligned.m16n8k16.row.col.f32.f16.f16.f32 "
                 "{%0,%1,%2,%3}, {%4,%5,%6,%7}, {%8,%9}, {%0,%1,%2,%3};"
                 : "+f"(c[0]), "+f"(c[1]), "+f"(c[2]), "+f"(c[3])
                 : "r"(a[0]), "r"(a[1]), "r"(a[2]), "r"(a[3]), "r"(b0), "r"(b1));
}

// ---------------------------------------------------------------------------
// Pre-pass A: enc_states fp32 -> fp16 (RN); 2 float4 per thread
// ---------------------------------------------------------------------------
__global__ void convert_enc(const float* __restrict__ enc) {
    size_t i = ((size_t)blockIdx.x * blockDim.x + threadIdx.x) * 2;
    #pragma unroll
    for (int j = 0; j < 2; j++) {
        float4 v = reinterpret_cast<const float4*>(enc)[i + j];
        __half2 p0 = __floats2half2_rn(v.x, v.y);
        __half2 p1 = __floats2half2_rn(v.z, v.w);
        uint2 u;
        u.x = *reinterpret_cast<uint32_t*>(&p0);
        u.y = *reinterpret_cast<uint32_t*>(&p1);
        reinterpret_cast<uint2*>(g_ench)[i + j] = u;
    }
}

// ---------------------------------------------------------------------------
// Pre-pass B: W_enc [K,N] fp32 -> transposed K-major fp16
// ---------------------------------------------------------------------------
__global__ void convert_W(const float* __restrict__ W) {
    int n = blockIdx.x;
    int k = threadIdx.x;
    g_WT[(size_t)n * Dn + k] = __float2half_rn(W[(size_t)k * Dn + n]);
}

// ---------------------------------------------------------------------------
// decb[b,c] = b_dec[c] + b_enc[c] + dec_states[b,:] @ W_dec[:,c]
// ---------------------------------------------------------------------------
__global__ void dech_kernel(const float* __restrict__ dec,
                            const float* __restrict__ Wdec,
                            const float* __restrict__ bdec,
                            const float* __restrict__ benc) {
    const int b   = blockIdx.x;
    const int c   = blockIdx.y * 256 + threadIdx.x;
    __shared__ float dsh[Dn];
    for (int k = threadIdx.x; k < Dn; k += 256) dsh[k] = dec[b * Dn + k];
    __syncthreads();
    float acc = bdec[c] + benc[c];
    #pragma unroll 8
    for (int k = 0; k < Dn; k++)
        acc = fmaf(dsh[k], Wdec[(size_t)k * Dn + c], acc);
    g_decb[b * Dn + c] = acc;
}

// ---------------------------------------------------------------------------
// HMMA fused score GEMM (fp16, BK=64, 3-stage ring; R13/R15 structure).
//  D[128,128] = A_fp16[128,K] @ B_fp16[128,K]^T  (fp32 accum)
//  epilogue: rowsum of tanh(D + decb) * w_attn -> g_scores_part[tile_n][row]
//  NEW: length-mask early exit. Rows s >= enc_len[b] are -inf-masked in
//  softmax and never consumed -> m-tiles fully beyond len[b] skip entirely
//  (E[skip] ~ 22% of CTAs; uniform per-CTA condition before any barrier).
//  Their g_scores_part region stays zero-init and is read-but-discarded.
// ---------------------------------------------------------------------------
struct Stage {
    __half A[BM][ROWP];    // 18432 B
    __half B[BN][ROWP];    // 18432 B
};
#define B_OFF  (BM * ROWP * 2)             // byte offset of B within a stage
#define SMEM_BYTES (NSTG * (int)sizeof(Stage) + (BN + BN + 2 * BM) * 4)

__global__ __launch_bounds__(256)
void score_gemm_hmma(const float* __restrict__ wattn,
                     const int* __restrict__ enc_len) {
    const int m0 = blockIdx.y * BM;
    const int b  = m0 >> 11;
    if ((m0 & (Sn - 1)) >= enc_len[b]) return;   // fully-masked m-tile

    extern __shared__ char dsm[];
    float* s_db   = reinterpret_cast<float*>(dsm + NSTG * sizeof(Stage));
    float* s_w    = s_db + BN;
    float* rowsum = s_w + BN;                 // [2][BM]

    const int tid  = threadIdx.x;
    const int wid  = tid >> 5;
    const int lane = tid & 31;
    const int wm   = wid >> 1;     // 0..3 : 32-row group
    const int wn   = wid & 1;      // 0..1 : 64-col group
    const int n0   = blockIdx.x * BN;   // x = col tile -> CTAs share A in L2

    if (tid < BN) {
        s_db[tid] = g_decb[b * Dn + n0 + tid];
        s_w[tid]  = wattn[n0 + tid];
    }

    float acc[2][8][4];            // [mi][nf][frag] : 64 regs
    #pragma unroll
    for (int i = 0; i < 2; i++)
        #pragma unroll
        for (int j = 0; j < 8; j++)
            #pragma unroll
            for (int q = 0; q < 4; q++) acc[i][j][q] = 0.f;

    // ---- hoisted loader addressing ----
    const int s8 = (tid & 7) * 8;             // half offset within 64-half row
    const int r0 = tid >> 3;                  // 0..31
    const __half* aSrc = g_ench + ((size_t)m0 + r0) * Dn + s8;
    const __half* bSrc = g_WT + (size_t)(n0 + r0) * Dn + s8;
    uint32_t stgAddr[NSTG];
    #pragma unroll
    for (int s = 0; s < NSTG; s++) stgAddr[s] = smem_u32(dsm + s * sizeof(Stage));
    const uint32_t aDst = r0 * (ROWP * 2) + s8 * 2;           // within stage
    const uint32_t bDst = B_OFF + r0 * (ROWP * 2) + s8 * 2;

    auto load_chunk = [&](int c) {
        const uint32_t base = stgAddr[c % NSTG];
        const int k0 = c * BK;
        #pragma unroll
        for (int i = 0; i < 4; i++)           // A: 4 x 32 rows
            cp_async16(base + aDst + i * (32 * ROWP * 2),
                       aSrc + k0 + (size_t)i * 32 * Dn);
        #pragma unroll
        for (int i = 0; i < 4; i++)           // B: 4 x 32 rows
            cp_async16(base + bDst + i * (32 * ROWP * 2),
                       bSrc + k0 + (size_t)i * 32 * Dn);
        cp_commit();
    };

    // ---- hoisted ldmatrix addressing ----
    const uint32_t aLd = (wm * 32 + (lane & 15)) * (ROWP * 2) + (lane >> 4) * 16;
    const int quad = lane >> 3;
    const uint32_t bLd = B_OFF
        + (wn * 64 + ((quad & 2) ? 8 : 0) + (lane & 7)) * (ROWP * 2)
        + ((quad & 1) ? 16 : 0);

    load_chunk(0);
    load_chunk(1);

    for (int c = 0; c < NCHUNK; c++) {
        cp_wait<1>();                 // chunk c landed (c+1 may stay in flight)
        __syncthreads();              // all warps see it; stage (c+2)%3 is free
        if (c + 2 < NCHUNK) load_chunk(c + 2);   // overlaps compute below
        const uint32_t base = stgAddr[c % NSTG];

        #pragma unroll
        for (int kk = 0; kk < 4; kk++) {              // four k16 steps per chunk
            const uint32_t kboff = kk * 32;           // kb*2 bytes
            uint32_t a[2][4];
            ldsm4(a[0], base + aLd + kboff);
            ldsm4(a[1], base + aLd + (16 * ROWP * 2) + kboff);
            uint32_t bf[4][4];
            ldsm4(bf[0], base + bLd + kboff);
            ldsm4(bf[1], base + bLd + (16 * ROWP * 2) + kboff);
            #pragma unroll
            for (int mi = 0; mi < 2; mi++) {
                mma16816(acc[mi][0], a[mi], bf[0][0], bf[0][1]);
                mma16816(acc[mi][1], a[mi], bf[0][2], bf[0][3]);
            }
            ldsm4(bf[2], base + bLd + 2 * (16 * ROWP * 2) + kboff);
            #pragma unroll
            for (int mi = 0; mi < 2; mi++) {
                mma16816(acc[mi][2], a[mi], bf[1][0], bf[1][1]);
                mma16816(acc[mi][3], a[mi], bf[1][2], bf[1][3]);
            }
            ldsm4(bf[3], base + bLd + 3 * (16 * ROWP * 2) + kboff);
            #pragma unroll
            for (int mi = 0; mi < 2; mi++) {
                mma16816(acc[mi][4], a[mi], bf[2][0], bf[2][1]);
                mma16816(acc[mi][5], a[mi], bf[2][2], bf[2][3]);
            }
            #pragma unroll
            for (int mi = 0; mi < 2; mi++) {
                mma16816(acc[mi][6], a[mi], bf[3][0], bf[3][1]);
                mma16816(acc[mi][7], a[mi], bf[3][2], bf[3][3]);
            }
        }
    }

    // Epilogue: rowsum of tanh(acc + decb) * w_attn
    // c-frag: c0,c1 -> row lane/4, cols 2*(lane%4)+{0,1}; c2,c3 -> row +8
    __syncthreads();                  // loads done; reuse of rowsum region safe
    #pragma unroll
    for (int mi = 0; mi < 2; mi++) {
        float sl = 0.f, sh = 0.f;
        #pragma unroll
        for (int nf = 0; nf < 8; nf++) {
            int cb = wn * 64 + nf * 8 + (lane & 3) * 2;
            sl += tanhf(acc[mi][nf][0] + s_db[cb])     * s_w[cb]
                + tanhf(acc[mi][nf][1] + s_db[cb + 1]) * s_w[cb + 1];
            sh += tanhf(acc[mi][nf][2] + s_db[cb])     * s_w[cb]
                + tanhf(acc[mi][nf][3] + s_db[cb + 1]) * s_w[cb + 1];
        }
        sl += __shfl_xor_sync(0xffffffffu, sl, 1);
        sl += __shfl_xor_sync(0xffffffffu, sl, 2);
        sh += __shfl_xor_sync(0xffffffffu, sh, 1);
        sh += __shfl_xor_sync(0xffffffffu, sh, 2);
        if ((lane & 3) == 0) {
            int r = wm * 32 + mi * 16 + (lane >> 2);
            rowsum[wn * BM + r]     = sl;
            rowsum[wn * BM + r + 8] = sh;
        }
    }
    __syncthreads();
    if (tid < BM)
        g_scores_part[blockIdx.x * Mn + m0 + tid] = rowsum[tid] + rowsum[BM + tid];
}

// ---------------------------------------------------------------------------
// Masked softmax per batch row; writes attn into d_out[32768 + b*2048 + s]
// (partials of fully-masked tiles are zero-init garbage but only touched for
//  s < len — never consumed)
// ---------------------------------------------------------------------------
__global__ void softmax_kernel(const int* __restrict__ enc_len,
                               float* __restrict__ attn_out) {
    const int b = blockIdx.x;
    const int tid = threadIdx.x;
    __shared__ float red[256];
    __shared__ float sc[Sn];

    const int len = enc_len[b];

    float lmax = -INFINITY;
    for (int s = tid; s < Sn; s += 256) {
        float v = 0.f;
        #pragma unroll
        for (int ct = 0; ct < NTILES; ct++)
            v += g_scores_part[ct * Mn + b * Sn + s];
        sc[s] = v;
        if (s < len) lmax = fmaxf(lmax, v);
    }
    red[tid] = lmax;
    __syncthreads();
    for (int off = 128; off > 0; off >>= 1) {
        if (tid < off) red[tid] = fmaxf(red[tid], red[tid + off]);
        __syncthreads();
    }
    const float m = red[0];
    __syncthreads();

    float lsum = 0.f;
    for (int s = tid; s < Sn; s += 256) {
        float e = (s < len) ? expf(sc[s] - m) : 0.f;
        sc[s] = e;
        lsum += e;
    }
    red[tid] = lsum;
    __syncthreads();
    for (int off = 128; off > 0; off >>= 1) {
        if (tid < off) red[tid] += red[tid + off];
        __syncthreads();
    }
    const float inv = 1.f / red[0];
    __syncthreads();

    for (int s = tid; s < Sn; s += 256)
        attn_out[b * Sn + s] = sc[s] * inv;
}

// ---------------------------------------------------------------------------
// Context partials: CCH=32 chunks x 64 s-steps, 256 thr x 4 dims, unroll 8
// (R15 version was 512 CTAs x 128 thr, un-unrolled 128-dep-load loop ->
//  DRAM-latency-bound). Fully-masked chunks write zeros and exit.
// ---------------------------------------------------------------------------
__global__ void context_kernel(const float* __restrict__ attn,
                               const int* __restrict__ enc_len) {
    const int ch  = blockIdx.x;     // 0..31
    const int b   = blockIdx.y;
    const int tid = threadIdx.x;    // 0..255
    const int d   = tid * 4;
    const int s0  = ch * 64;
    float* dst = &g_ctx_part[((size_t)ch * Bn + b) * Dn + d];

    if (s0 >= enc_len[b]) {         // fully masked: attn==0 here
        *reinterpret_cast<float4*>(dst) = make_float4(0.f, 0.f, 0.f, 0.f);
        return;
    }

    __shared__ float wsh[64];
    if (tid < 64) wsh[tid] = attn[b * Sn + s0 + tid];
    __syncthreads();

    float4 acc = make_float4(0.f, 0.f, 0.f, 0.f);
    const __half* __restrict__ ebase = g_ench + ((size_t)b * Sn + s0) * Dn + d;
    #pragma unroll 8
    for (int i = 0; i < 64; i++) {
        float w = wsh[i];
        uint2 raw = *reinterpret_cast<const uint2*>(ebase + (size_t)i * Dn);
        const __half2* h2 = reinterpret_cast<const __half2*>(&raw);
        float2 f0 = __half22float2(h2[0]);
        float2 f1 = __half22float2(h2[1]);
        acc.x = fmaf(w, f0.x, acc.x);
        acc.y = fmaf(w, f0.y, acc.y);
        acc.z = fmaf(w, f1.x, acc.z);
        acc.w = fmaf(w, f1.y, acc.w);
    }
    *reinterpret_cast<float4*>(dst) = acc;
}

// ---------------------------------------------------------------------------
// Output GEMM (sums CCH=32 context chunks)
// ---------------------------------------------------------------------------
__global__ void out_kernel(const float* __restrict__ Wout,
                           const float* __restrict__ bout,
                           float* __restrict__ out) {
    const int b = blockIdx.x;
    const int c = blockIdx.y * 256 + threadIdx.x;
    __shared__ float ctx[Dn];
    for (int k = threadIdx.x; k < Dn; k += 256) {
        float v = 0.f;
        #pragma unroll
        for (int ch = 0; ch < CCH; ch++)
            v += g_ctx_part[((size_t)ch * Bn + b) * Dn + k];
        ctx[k] = v;
    }
    __syncthreads();
    float acc = bout[c];
    #pragma unroll 8
    for (int k = 0; k < Dn; k++)
        acc = fmaf(ctx[k], Wout[(size_t)k * Dn + c], acc);
    out[b * Dn + c] = acc;
}

// ---------------------------------------------------------------------------
// Launch
// ---------------------------------------------------------------------------
extern "C" void kernel_launch(void* const* d_in, const int* in_sizes, int n_in,
                              void* d_out, int out_size) {
    const float* enc   = (const float*)d_in[0];
    const float* dec   = (const float*)d_in[1];
    const float* Wenc  = (const float*)d_in[2];
    const float* benc  = (const float*)d_in[3];
    const float* Wdec  = (const float*)d_in[4];
    const float* bdec  = (const float*)d_in[5];
    const float* wattn = (const float*)d_in[6];
    const float* Wout  = (const float*)d_in[7];
    const float* bout  = (const float*)d_in[8];
    const int*   elen  = (const int*)d_in[9];

    float* out      = (float*)d_out;       // context [32*1024]
    float* attn_out = out + Bn * Dn;       // attn    [32*2048]

    cudaFuncSetAttribute(score_gemm_hmma,
                         cudaFuncAttributeMaxDynamicSharedMemorySize, SMEM_BYTES);

    convert_enc<<<(Mn * (Dn / 4)) / 512, 256>>>(enc);
    convert_W<<<Dn, Dn>>>(Wenc);
    dech_kernel<<<dim3(Bn, 4), 256>>>(dec, Wdec, bdec, benc);
    score_gemm_hmma<<<dim3(NTILES, Mn / BM), 256, SMEM_BYTES>>>(wattn, elen);
    softmax_kernel<<<Bn, 256>>>(elen, attn_out);
    context_kernel<<<dim3(CCH, Bn), 256>>>(attn_out, elen);
    out_kernel<<<dim3(Bn, 4), 256>>>(Wout, bout, out);
}

// round 17
// speedup vs baseline: 1.7796x; 1.0489x over previous
#include <cuda_runtime.h>
#include <cuda_fp16.h>
#include <cstdint>
#include <math.h>

// Problem constants
#define Bn   32
#define Sn   2048
#define Dn   1024
#define Mn   (Bn * Sn)

// Score-GEMM tiling (mma.sync HMMA path — tcgen05 PTX is rejected by the
// harness's compute_103 PTX stage, so we use the arch-portable tensor path)
#define BM 128              // CTA rows  (8 warps: 4M x 2N, warp tile 32x64)
#define BN 128              // CTA cols
#define BK 64               // K per chunk
#define NTILES (Dn / BN)    // 8 column tiles
#define NCHUNK (Dn / BK)    // 16 chunks
#define NSTG 3              // 3-stage ring -> single barrier per chunk

#define ROWP 72             // SMEM row stride in halves (144 B = 36 banks ≡ 4
                            // mod 32 -> ldmatrix phases conflict-free)

#define CCH 32              // context: 32 chunks of 64 seq positions

// prep_kernel grid partition
#define PREP_ENC 32768      // enc convert CTAs (2 rows each)
#define PREP_W   1024       // W transpose 32x32 tiles
#define PREP_DEC 128        // dech CTAs

// ---------------------------------------------------------------------------
// Scratch (static device globals; no allocation allowed)
// ---------------------------------------------------------------------------
__device__ float g_decb[Bn * Dn];                    // dec_h + b_dec + b_enc
__device__ float g_scores_part[NTILES * Mn];         // per-col-tile score partials
__device__ float g_ctx_part[CCH * Bn * Dn];          // context partials
__device__ __half g_ench[(size_t)Mn * Dn];           // enc_states fp16 (128 MB)
__device__ __half g_WT[Dn * Dn];                     // W_enc^T fp16 (K-major: [n][k])

// ---------------------------------------------------------------------------
// PTX helpers (sm_80-compatible only: cp.async, ldmatrix, mma.sync)
// ---------------------------------------------------------------------------
__device__ __forceinline__ uint32_t smem_u32(const void* p) {
    uint32_t a;
    asm("{ .reg .u64 t; cvta.to.shared.u64 t, %1; cvt.u32.u64 %0, t; }" : "=r"(a) : "l"(p));
    return a;
}
__device__ __forceinline__ void cp_async16(uint32_t dst, const void* src) {
    asm volatile("cp.async.cg.shared.global [%0], [%1], 16;" :: "r"(dst), "l"(src));
}
__device__ __forceinline__ void cp_commit() {
    asm volatile("cp.async.commit_group;" ::: "memory");
}
template <int N>
__device__ __forceinline__ void cp_wait() {
    asm volatile("cp.async.wait_group %0;" :: "n"(N) : "memory");
}
__device__ __forceinline__ void ldsm4(uint32_t* r, uint32_t addr) {
    asm volatile("ldmatrix.sync.aligned.m8n8.x4.shared.b16 {%0,%1,%2,%3}, [%4];"
                 : "=r"(r[0]), "=r"(r[1]), "=r"(r[2]), "=r"(r[3]) : "r"(addr));
}
__device__ __forceinline__ void mma16816(float* c, const uint32_t* a,
                                         uint32_t b0, uint32_t b1) {
    asm volatile("mma.sync.aligned.m16n8k16.row.col.f32.f16.f16.f32 "
                 "{%0,%1,%2,%3}, {%4,%5,%6,%7}, {%8,%9}, {%0,%1,%2,%3};"
                 : "+f"(c[0]), "+f"(c[1]), "+f"(c[2]), "+f"(c[3])
                 : "r"(a[0]), "r"(a[1]), "r"(a[2]), "r"(a[3]), "r"(b0), "r"(b1));
}

// ---------------------------------------------------------------------------
// Fused prep kernel: enc fp32->fp16 (length-skipped) | W transpose | dec MLP.
// One launch instead of three: removes 2 graph gaps, overlaps the DRAM-bound
// enc conversion with the L2-bound dech GEMV. The old convert_W read W with
// 4KB-strided 4B loads (32x sector amplification, ~128MB effective traffic);
// now a 32x32 smem tile transpose with coalesced 128B reads.
// ---------------------------------------------------------------------------
__global__ __launch_bounds__(256)
void prep_kernel(const float* __restrict__ enc,
                 const float* __restrict__ W,
                 const float* __restrict__ dec,
                 const float* __restrict__ Wdec,
                 const float* __restrict__ bdec,
                 const float* __restrict__ benc,
                 const int* __restrict__ elen) {
    __shared__ float sbuf[1088];      // max(32*33 transpose tile, 1024 dech)
    const int bx  = blockIdx.x;
    const int tid = threadIdx.x;

    if (bx < PREP_ENC) {
        // ---- enc_states fp32 -> fp16; skip rows >= ceil(len/128)*128 ----
        // (those rows are never read: score m-tiles there are skipped and
        //  context chunks there are masked)
        const int b  = bx >> 10;                  // 1024 CTAs per batch
        const int s0 = (bx & 1023) * 2;           // 2 rows per CTA
        const int lim = (elen[b] + 127) & ~127;
        if (s0 >= lim) return;
        size_t i = ((size_t)bx * 256 + tid) * 2;  // float4 index
        #pragma unroll
        for (int j = 0; j < 2; j++) {
            float4 v = reinterpret_cast<const float4*>(enc)[i + j];
            __half2 p0 = __floats2half2_rn(v.x, v.y);
            __half2 p1 = __floats2half2_rn(v.z, v.w);
            uint2 u;
            u.x = *reinterpret_cast<uint32_t*>(&p0);
            u.y = *reinterpret_cast<uint32_t*>(&p1);
            reinterpret_cast<uint2*>(g_ench)[i + j] = u;
        }
    } else if (bx < PREP_ENC + PREP_W) {
        // ---- W_enc [K,N] -> g_WT [N,K] fp16, 32x32 tile via smem ----
        const int t  = bx - PREP_ENC;
        const int tr = t >> 5;                    // k-tile
        const int tc = t & 31;                    // n-tile
        float (*tile)[33] = reinterpret_cast<float(*)[33]>(sbuf);
        const int rl = tid >> 3;                  // 0..31 row (k_local)
        const int c4 = (tid & 7) * 4;             // col offset (n_local)
        float4 v = *reinterpret_cast<const float4*>(
            &W[(size_t)(tr * 32 + rl) * Dn + tc * 32 + c4]);
        tile[rl][c4] = v.x; tile[rl][c4 + 1] = v.y;
        tile[rl][c4 + 2] = v.z; tile[rl][c4 + 3] = v.w;
        __syncthreads();
        const int nl = tid >> 3;                  // 0..31 n_local
        const int h4 = (tid & 7) * 4;             // k_local offset
        __half2 h0 = __floats2half2_rn(tile[h4][nl], tile[h4 + 1][nl]);
        __half2 h1 = __floats2half2_rn(tile[h4 + 2][nl], tile[h4 + 3][nl]);
        uint2 u;
        u.x = *reinterpret_cast<uint32_t*>(&h0);
        u.y = *reinterpret_cast<uint32_t*>(&h1);
        *reinterpret_cast<uint2*>(
            &g_WT[(size_t)(tc * 32 + nl) * Dn + tr * 32 + h4]) = u;
    } else {
        // ---- decb[b,c] = b_dec[c]+b_enc[c] + dec[b,:]@Wdec[:,c] ----
        const int idx = bx - (PREP_ENC + PREP_W);
        const int b = idx >> 2;
        const int c = (idx & 3) * 256 + tid;
        float* dsh = sbuf;
        for (int k = tid; k < Dn; k += 256) dsh[k] = dec[b * Dn + k];
        __syncthreads();
        float acc = bdec[c] + benc[c];
        #pragma unroll 8
        for (int k = 0; k < Dn; k++)
            acc = fmaf(dsh[k], Wdec[(size_t)k * Dn + c], acc);
        g_decb[b * Dn + c] = acc;
    }
}

// ---------------------------------------------------------------------------
// HMMA fused score GEMM (fp16, BK=64, 3-stage ring; R13/R15 structure).
//  D[128,128] = A_fp16[128,K] @ B_fp16[128,K]^T  (fp32 accum)
//  epilogue: rowsum of tanh(D + decb) * w_attn -> g_scores_part[tile_n][row]
//  Length-mask early exit: m-tiles fully beyond len[b] skip entirely.
// ---------------------------------------------------------------------------
struct Stage {
    __half A[BM][ROWP];    // 18432 B
    __half B[BN][ROWP];    // 18432 B
};
#define B_OFF  (BM * ROWP * 2)             // byte offset of B within a stage
#define SMEM_BYTES (NSTG * (int)sizeof(Stage) + (BN + BN + 2 * BM) * 4)

__global__ __launch_bounds__(256)
void score_gemm_hmma(const float* __restrict__ wattn,
                     const int* __restrict__ enc_len) {
    const int m0 = blockIdx.y * BM;
    const int b  = m0 >> 11;
    if ((m0 & (Sn - 1)) >= enc_len[b]) return;   // fully-masked m-tile

    extern __shared__ char dsm[];
    float* s_db   = reinterpret_cast<float*>(dsm + NSTG * sizeof(Stage));
    float* s_w    = s_db + BN;
    float* rowsum = s_w + BN;                 // [2][BM]

    const int tid  = threadIdx.x;
    const int wid  = tid >> 5;
    const int lane = tid & 31;
    const int wm   = wid >> 1;     // 0..3 : 32-row group
    const int wn   = wid & 1;      // 0..1 : 64-col group
    const int n0   = blockIdx.x * BN;   // x = col tile -> CTAs share A in L2

    if (tid < BN) {
        s_db[tid] = g_decb[b * Dn + n0 + tid];
        s_w[tid]  = wattn[n0 + tid];
    }

    float acc[2][8][4];            // [mi][nf][frag] : 64 regs
    #pragma unroll
    for (int i = 0; i < 2; i++)
        #pragma unroll
        for (int j = 0; j < 8; j++)
            #pragma unroll
            for (int q = 0; q < 4; q++) acc[i][j][q] = 0.f;

    // ---- hoisted loader addressing ----
    const int s8 = (tid & 7) * 8;             // half offset within 64-half row
    const int r0 = tid >> 3;                  // 0..31
    const __half* aSrc = g_ench + ((size_t)m0 + r0) * Dn + s8;
    const __half* bSrc = g_WT + (size_t)(n0 + r0) * Dn + s8;
    uint32_t stgAddr[NSTG];
    #pragma unroll
    for (int s = 0; s < NSTG; s++) stgAddr[s] = smem_u32(dsm + s * sizeof(Stage));
    const uint32_t aDst = r0 * (ROWP * 2) + s8 * 2;           // within stage
    const uint32_t bDst = B_OFF + r0 * (ROWP * 2) + s8 * 2;

    auto load_chunk = [&](int c) {
        const uint32_t base = stgAddr[c % NSTG];
        const int k0 = c * BK;
        #pragma unroll
        for (int i = 0; i < 4; i++)           // A: 4 x 32 rows
            cp_async16(base + aDst + i * (32 * ROWP * 2),
                       aSrc + k0 + (size_t)i * 32 * Dn);
        #pragma unroll
        for (int i = 0; i < 4; i++)           // B: 4 x 32 rows
            cp_async16(base + bDst + i * (32 * ROWP * 2),
                       bSrc + k0 + (size_t)i * 32 * Dn);
        cp_commit();
    };

    // ---- hoisted ldmatrix addressing ----
    const uint32_t aLd = (wm * 32 + (lane & 15)) * (ROWP * 2) + (lane >> 4) * 16;
    const int quad = lane >> 3;
    const uint32_t bLd = B_OFF
        + (wn * 64 + ((quad & 2) ? 8 : 0) + (lane & 7)) * (ROWP * 2)
        + ((quad & 1) ? 16 : 0);

    load_chunk(0);
    load_chunk(1);

    for (int c = 0; c < NCHUNK; c++) {
        cp_wait<1>();                 // chunk c landed (c+1 may stay in flight)
        __syncthreads();              // all warps see it; stage (c+2)%3 is free
        if (c + 2 < NCHUNK) load_chunk(c + 2);   // overlaps compute below
        const uint32_t base = stgAddr[c % NSTG];

        #pragma unroll
        for (int kk = 0; kk < 4; kk++) {              // four k16 steps per chunk
            const uint32_t kboff = kk * 32;           // kb*2 bytes
            uint32_t a[2][4];
            ldsm4(a[0], base + aLd + kboff);
            ldsm4(a[1], base + aLd + (16 * ROWP * 2) + kboff);
            uint32_t bf[4][4];
            ldsm4(bf[0], base + bLd + kboff);
            ldsm4(bf[1], base + bLd + (16 * ROWP * 2) + kboff);
            #pragma unroll
            for (int mi = 0; mi < 2; mi++) {
                mma16816(acc[mi][0], a[mi], bf[0][0], bf[0][1]);
                mma16816(acc[mi][1], a[mi], bf[0][2], bf[0][3]);
            }
            ldsm4(bf[2], base + bLd + 2 * (16 * ROWP * 2) + kboff);
            #pragma unroll
            for (int mi = 0; mi < 2; mi++) {
                mma16816(acc[mi][2], a[mi], bf[1][0], bf[1][1]);
                mma16816(acc[mi][3], a[mi], bf[1][2], bf[1][3]);
            }
            ldsm4(bf[3], base + bLd + 3 * (16 * ROWP * 2) + kboff);
            #pragma unroll
            for (int mi = 0; mi < 2; mi++) {
                mma16816(acc[mi][4], a[mi], bf[2][0], bf[2][1]);
                mma16816(acc[mi][5], a[mi], bf[2][2], bf[2][3]);
            }
            #pragma unroll
            for (int mi = 0; mi < 2; mi++) {
                mma16816(acc[mi][6], a[mi], bf[3][0], bf[3][1]);
                mma16816(acc[mi][7], a[mi], bf[3][2], bf[3][3]);
            }
        }
    }

    // Epilogue: rowsum of tanh(acc + decb) * w_attn
    // c-frag: c0,c1 -> row lane/4, cols 2*(lane%4)+{0,1}; c2,c3 -> row +8
    __syncthreads();                  // loads done; reuse of rowsum region safe
    #pragma unroll
    for (int mi = 0; mi < 2; mi++) {
        float sl = 0.f, sh = 0.f;
        #pragma unroll
        for (int nf = 0; nf < 8; nf++) {
            int cb = wn * 64 + nf * 8 + (lane & 3) * 2;
            sl += tanhf(acc[mi][nf][0] + s_db[cb])     * s_w[cb]
                + tanhf(acc[mi][nf][1] + s_db[cb + 1]) * s_w[cb + 1];
            sh += tanhf(acc[mi][nf][2] + s_db[cb])     * s_w[cb]
                + tanhf(acc[mi][nf][3] + s_db[cb + 1]) * s_w[cb + 1];
        }
        sl += __shfl_xor_sync(0xffffffffu, sl, 1);
        sl += __shfl_xor_sync(0xffffffffu, sl, 2);
        sh += __shfl_xor_sync(0xffffffffu, sh, 1);
        sh += __shfl_xor_sync(0xffffffffu, sh, 2);
        if ((lane & 3) == 0) {
            int r = wm * 32 + mi * 16 + (lane >> 2);
            rowsum[wn * BM + r]     = sl;
            rowsum[wn * BM + r + 8] = sh;
        }
    }
    __syncthreads();
    if (tid < BM)
        g_scores_part[blockIdx.x * Mn + m0 + tid] = rowsum[tid] + rowsum[BM + tid];
}

// ---------------------------------------------------------------------------
// Masked softmax per batch row; writes attn into d_out[32768 + b*2048 + s]
// ---------------------------------------------------------------------------
__global__ void softmax_kernel(const int* __restrict__ enc_len,
                               float* __restrict__ attn_out) {
    const int b = blockIdx.x;
    const int tid = threadIdx.x;
    __shared__ float red[256];
    __shared__ float sc[Sn];

    const int len = enc_len[b];

    float lmax = -INFINITY;
    for (int s = tid; s < Sn; s += 256) {
        float v = 0.f;
        #pragma unroll
        for (int ct = 0; ct < NTILES; ct++)
            v += g_scores_part[ct * Mn + b * Sn + s];
        sc[s] = v;
        if (s < len) lmax = fmaxf(lmax, v);
    }
    red[tid] = lmax;
    __syncthreads();
    for (int off = 128; off > 0; off >>= 1) {
        if (tid < off) red[tid] = fmaxf(red[tid], red[tid + off]);
        __syncthreads();
    }
    const float m = red[0];
    __syncthreads();

    float lsum = 0.f;
    for (int s = tid; s < Sn; s += 256) {
        float e = (s < len) ? expf(sc[s] - m) : 0.f;
        sc[s] = e;
        lsum += e;
    }
    red[tid] = lsum;
    __syncthreads();
    for (int off = 128; off > 0; off >>= 1) {
        if (tid < off) red[tid] += red[tid + off];
        __syncthreads();
    }
    const float inv = 1.f / red[0];
    __syncthreads();

    for (int s = tid; s < Sn; s += 256)
        attn_out[b * Sn + s] = sc[s] * inv;
}

// ---------------------------------------------------------------------------
// Context partials: CCH=32 chunks x 64 s-steps, 256 thr x 4 dims, unroll 8.
// Fully-masked chunks write zeros and exit.
// ---------------------------------------------------------------------------
__global__ void context_kernel(const float* __restrict__ attn,
                               const int* __restrict__ enc_len) {
    const int ch  = blockIdx.x;     // 0..31
    const int b   = blockIdx.y;
    const int tid = threadIdx.x;    // 0..255
    const int d   = tid * 4;
    const int s0  = ch * 64;
    float* dst = &g_ctx_part[((size_t)ch * Bn + b) * Dn + d];

    if (s0 >= enc_len[b]) {         // fully masked: attn==0 here
        *reinterpret_cast<float4*>(dst) = make_float4(0.f, 0.f, 0.f, 0.f);
        return;
    }

    __shared__ float wsh[64];
    if (tid < 64) wsh[tid] = attn[b * Sn + s0 + tid];
    __syncthreads();

    float4 acc = make_float4(0.f, 0.f, 0.f, 0.f);
    const __half* __restrict__ ebase = g_ench + ((size_t)b * Sn + s0) * Dn + d;
    #pragma unroll 8
    for (int i = 0; i < 64; i++) {
        float w = wsh[i];
        uint2 raw = *reinterpret_cast<const uint2*>(ebase + (size_t)i * Dn);
        const __half2* h2 = reinterpret_cast<const __half2*>(&raw);
        float2 f0 = __half22float2(h2[0]);
        float2 f1 = __half22float2(h2[1]);
        acc.x = fmaf(w, f0.x, acc.x);
        acc.y = fmaf(w, f0.y, acc.y);
        acc.z = fmaf(w, f1.x, acc.z);
        acc.w = fmaf(w, f1.y, acc.w);
    }
    *reinterpret_cast<float4*>(dst) = acc;
}

// ---------------------------------------------------------------------------
// Output GEMM (sums CCH=32 context chunks)
// ---------------------------------------------------------------------------
__global__ void out_kernel(const float* __restrict__ Wout,
                           const float* __restrict__ bout,
                           float* __restrict__ out) {
    const int b = blockIdx.x;
    const int c = blockIdx.y * 256 + threadIdx.x;
    __shared__ float ctx[Dn];
    for (int k = threadIdx.x; k < Dn; k += 256) {
        float v = 0.f;
        #pragma unroll
        for (int ch = 0; ch < CCH; ch++)
            v += g_ctx_part[((size_t)ch * Bn + b) * Dn + k];
        ctx[k] = v;
    }
    __syncthreads();
    float acc = bout[c];
    #pragma unroll 8
    for (int k = 0; k < Dn; k++)
        acc = fmaf(ctx[k], Wout[(size_t)k * Dn + c], acc);
    out[b * Dn + c] = acc;
}

// ---------------------------------------------------------------------------
// Launch
// ---------------------------------------------------------------------------
extern "C" void kernel_launch(void* const* d_in, const int* in_sizes, int n_in,
                              void* d_out, int out_size) {
    const float* enc   = (const float*)d_in[0];
    const float* dec   = (const float*)d_in[1];
    const float* Wenc  = (const float*)d_in[2];
    const float* benc  = (const float*)d_in[3];
    const float* Wdec  = (const float*)d_in[4];
    const float* bdec  = (const float*)d_in[5];
    const float* wattn = (const float*)d_in[6];
    const float* Wout  = (const float*)d_in[7];
    const float* bout  = (const float*)d_in[8];
    const int*   elen  = (const int*)d_in[9];

    float* out      = (float*)d_out;       // context [32*1024]
    float* attn_out = out + Bn * Dn;       // attn    [32*2048]

    cudaFuncSetAttribute(score_gemm_hmma,
                         cudaFuncAttributeMaxDynamicSharedMemorySize, SMEM_BYTES);

    prep_kernel<<<PREP_ENC + PREP_W + PREP_DEC, 256>>>(
        enc, Wenc, dec, Wdec, bdec, benc, elen);
    score_gemm_hmma<<<dim3(NTILES, Mn / BM), 256, SMEM_BYTES>>>(wattn, elen);
    softmax_kernel<<<Bn, 256>>>(elen, attn_out);
    context_kernel<<<dim3(CCH, Bn), 256>>>(attn_out, elen);
    out_kernel<<<dim3(Bn, 4), 256>>>(Wout, bout, out);
}